// round 2
// baseline (speedup 1.0000x reference)
#include <cuda_runtime.h>

#define NN 50000
#define EE 800000
#define DH 128
#define DE 16
#define LLAY 3

typedef unsigned long long u64;

// ---------- packed f32x2 helpers (sm_103a FFMA2: 2x tput vs scalar FFMA) ----------
__device__ __forceinline__ u64 pk2(float x, float y) {
    u64 r;
    asm("mov.b64 %0, {%1, %2};" : "=l"(r) : "r"(__float_as_uint(x)), "r"(__float_as_uint(y)));
    return r;
}
__device__ __forceinline__ float2 up2(u64 v) {
    unsigned lo, hi;
    asm("mov.b64 {%0, %1}, %2;" : "=r"(lo), "=r"(hi) : "l"(v));
    return make_float2(__uint_as_float(lo), __uint_as_float(hi));
}
__device__ __forceinline__ u64 ffma2(u64 a, u64 b, u64 c) {
    u64 d;
    asm("fma.rn.f32x2 %0, %1, %2, %3;" : "=l"(d) : "l"(a), "l"(b), "l"(c));
    return d;
}

// ---------- device scratch (no allocs allowed) ----------
__device__ int   g_deg[NN];
__device__ int   g_rowptr[NN + 1];
__device__ int   g_cursor[NN];
__device__ float g_dis[NN];
__device__ int   g_rowS[EE];                    // source node, CSR(dst) order
__device__ float g_wS[EE];                      // norm weight, CSR(dst) order
__device__ float g_eaS[(size_t)EE * DE];        // edge_attr, CSR(dst) order (51.2MB)
__device__ float g_S[(size_t)NN * DH * LLAY];   // segsum of relu hidden, 3 layers (76.8MB)
__device__ float g_hx[(size_t)NN * DH];
__device__ float g_Q[(size_t)NN * DH];
__device__ float g_h[(size_t)NN * DH];

// ---------- CSR build ----------
__global__ void k_zero() {
    int i = blockIdx.x * blockDim.x + threadIdx.x;
    if (i < NN) g_deg[i] = 0;
}

__global__ void k_hist(const int* __restrict__ col) {
    int e = blockIdx.x * blockDim.x + threadIdx.x;
    if (e < EE) atomicAdd(&g_deg[col[e]], 1);
}

__global__ void k_dis() {
    int i = blockIdx.x * blockDim.x + threadIdx.x;
    if (i < NN) {
        int d = g_deg[i];
        g_dis[i] = (d > 0) ? rsqrtf((float)d) : 0.0f;
    }
}

// single-block exclusive scan of g_deg -> g_rowptr / g_cursor (warp-shfl based)
__global__ void k_scan() {
    __shared__ int sh[32];
    int tid  = threadIdx.x;        // 1024 threads
    int lane = tid & 31, wid = tid >> 5;
    int carry = 0;
    for (int base = 0; base < NN; base += 1024) {
        int i = base + tid;
        int v = (i < NN) ? g_deg[i] : 0;
        int x = v;
        #pragma unroll
        for (int off = 1; off < 32; off <<= 1) {
            int t = __shfl_up_sync(0xffffffffu, x, off);
            if (lane >= off) x += t;
        }
        if (lane == 31) sh[wid] = x;
        __syncthreads();
        if (wid == 0) {
            int y = sh[lane];
            #pragma unroll
            for (int off = 1; off < 32; off <<= 1) {
                int t = __shfl_up_sync(0xffffffffu, y, off);
                if (lane >= off) y += t;
            }
            sh[lane] = y;
        }
        __syncthreads();
        int incl  = x + ((wid > 0) ? sh[wid - 1] : 0);
        int total = sh[31];
        if (i < NN) {
            int excl = incl - v + carry;
            g_rowptr[i] = excl;
            g_cursor[i] = excl;
        }
        carry += total;
        __syncthreads();
    }
    if (tid == 0) g_rowptr[NN] = carry;
}

__global__ void k_scatter(const int* __restrict__ row, const int* __restrict__ col,
                          const float* __restrict__ ea) {
    int e = blockIdx.x * blockDim.x + threadIdx.x;
    if (e >= EE) return;
    int c = col[e];
    int r = row[e];
    int pos = atomicAdd(&g_cursor[c], 1);
    g_rowS[pos] = r;
    g_wS[pos]   = g_dis[r] * g_dis[c];
    const float4* s = (const float4*)(ea + (size_t)e * DE);
    float4* d = (float4*)(g_eaS + (size_t)pos * DE);
    d[0] = s[0]; d[1] = s[1]; d[2] = s[2]; d[3] = s[3];
}

// ---------- edge-MLP hidden + segment sum: S[v, l*128+d] = sum_e relu(ea@W1_l + b1_l) ----------
// one warp per (node, layer); W1 column slice held in registers, ea broadcast via shfl
__global__ void k_spass(const float* __restrict__ ew1, const float* __restrict__ eb1) {
    int gw   = (blockIdx.x * blockDim.x + threadIdx.x) >> 5;
    int lane = threadIdx.x & 31;
    if (gw >= NN * LLAY) return;
    int v = gw / LLAY;
    int l = gw - v * LLAY;
    int d0 = lane * 4;

    u64 w1lo[16], w1hi[16];
    const float* W1 = ew1 + (size_t)l * DE * DH;
    #pragma unroll
    for (int k = 0; k < 16; k++) {
        float4 t = *(const float4*)(W1 + k * DH + d0);
        w1lo[k] = pk2(t.x, t.y);
        w1hi[k] = pk2(t.z, t.w);
    }
    float4 b1 = *(const float4*)(eb1 + l * DH + d0);
    u64 b1lo = pk2(b1.x, b1.y), b1hi = pk2(b1.z, b1.w);

    float a0 = 0.f, a1 = 0.f, a2 = 0.f, a3 = 0.f;
    int e0 = g_rowptr[v], e1 = g_rowptr[v + 1];
    for (int e = e0; e < e1; e++) {
        float eav = (lane < 16) ? g_eaS[(size_t)e * DE + lane] : 0.0f;
        u64 plo = b1lo, phi = b1hi;
        #pragma unroll
        for (int k = 0; k < 16; k++) {
            float ak = __shfl_sync(0xffffffffu, eav, k);
            u64 ak2 = pk2(ak, ak);
            plo = ffma2(ak2, w1lo[k], plo);
            phi = ffma2(ak2, w1hi[k], phi);
        }
        float2 x0 = up2(plo), x1 = up2(phi);
        a0 += fmaxf(x0.x, 0.f);
        a1 += fmaxf(x0.y, 0.f);
        a2 += fmaxf(x1.x, 0.f);
        a3 += fmaxf(x1.y, 0.f);
    }
    *(float4*)(g_S + (size_t)v * (DH * LLAY) + l * DH + d0) = make_float4(a0, a1, a2, a3);
}

// ---------- dense GEMM: C[M,128] = A[M,128(+stride lda)] @ B[128,128]  (f32, k-packed FFMA2) ----------
__global__ void k_gemm(const float* __restrict__ A, int lda,
                       const float* __restrict__ B,
                       float* __restrict__ C, int M) {
    extern __shared__ float sm[];
    float* As = sm;                      // 64 x 128 f32 (32KB)
    u64* Bsp  = (u64*)(sm + 64 * 128);   // [64 kk][128 c] k-paired (64KB)
    int tid = threadIdx.x;               // 256
    int m0  = blockIdx.x * 64;

    #pragma unroll
    for (int i = 0; i < 8; i++) {
        int lin = (i * 256 + tid) * 4;
        int r = lin >> 7, k = lin & 127;
        float4 vv = make_float4(0.f, 0.f, 0.f, 0.f);
        if (m0 + r < M) vv = *(const float4*)(A + (size_t)(m0 + r) * lda + k);
        *(float4*)(As + lin) = vv;
    }
    #pragma unroll
    for (int i = 0; i < 32; i++) {
        int idx = i * 256 + tid;
        int kk = idx >> 7, c = idx & 127;
        Bsp[idx] = pk2(B[(2 * kk) * 128 + c], B[(2 * kk + 1) * 128 + c]);
    }
    __syncthreads();

    int cbase = (tid & 31) * 4;   // all lanes of a warp share rows -> As loads broadcast
    int rbase = (tid >> 5) * 8;
    u64 acc[8][4];
    #pragma unroll
    for (int i = 0; i < 8; i++) {
        acc[i][0] = 0ull; acc[i][1] = 0ull; acc[i][2] = 0ull; acc[i][3] = 0ull;
    }
    const u64* Asd = (const u64*)As;     // k-pairs of A rows (row-major => contiguous)
    #pragma unroll 8
    for (int kk = 0; kk < 64; kk++) {
        const ulonglong2* bp = (const ulonglong2*)(Bsp + kk * 128 + cbase);
        ulonglong2 b01 = bp[0];
        ulonglong2 b23 = bp[1];
        #pragma unroll
        for (int i = 0; i < 8; i++) {
            u64 a = Asd[(size_t)(rbase + i) * 64 + kk];
            acc[i][0] = ffma2(a, b01.x, acc[i][0]);
            acc[i][1] = ffma2(a, b01.y, acc[i][1]);
            acc[i][2] = ffma2(a, b23.x, acc[i][2]);
            acc[i][3] = ffma2(a, b23.y, acc[i][3]);
        }
    }
    #pragma unroll
    for (int i = 0; i < 8; i++) {
        int r = m0 + rbase + i;
        if (r < M) {
            float2 t0 = up2(acc[i][0]), t1 = up2(acc[i][1]);
            float2 t2 = up2(acc[i][2]), t3 = up2(acc[i][3]);
            float4 o = make_float4(t0.x + t0.y, t1.x + t1.y, t2.x + t2.y, t3.x + t3.y);
            *(float4*)(C + (size_t)r * 128 + cbase) = o;
        }
    }
}

// ---------- gather + aggregate + LayerNorm + ReLU (one warp per node) ----------
__global__ void k_msgln(const float* __restrict__ hx, const float* __restrict__ Q,
                        const float* __restrict__ b2, const float* __restrict__ bi,
                        const float* __restrict__ lw, const float* __restrict__ lb,
                        float* __restrict__ out) {
    int gt = blockIdx.x * blockDim.x + threadIdx.x;
    int v = gt >> 5, lane = gt & 31;
    if (v >= NN) return;
    int d0 = lane * 4;
    float a0 = 0.f, a1 = 0.f, a2 = 0.f, a3 = 0.f;
    int e0 = g_rowptr[v], e1 = g_rowptr[v + 1];
    for (int base = e0; base < e1; base += 32) {
        int idx = base + lane;
        int   rr = (idx < e1) ? g_rowS[idx] : 0;
        float ww = (idx < e1) ? g_wS[idx] : 0.f;
        int n = min(32, e1 - base);
        #pragma unroll 4
        for (int j = 0; j < n; j++) {
            int   r = __shfl_sync(0xffffffffu, rr, j);
            float w = __shfl_sync(0xffffffffu, ww, j);
            float4 hv = *(const float4*)(hx + (size_t)r * 128 + d0);
            a0 = fmaf(w, hv.x, a0);
            a1 = fmaf(w, hv.y, a1);
            a2 = fmaf(w, hv.z, a2);
            a3 = fmaf(w, hv.w, a3);
        }
    }
    float degf = (float)g_deg[v];
    float4 q  = *(const float4*)(Q + (size_t)v * 128 + d0);
    float4 c2 = *(const float4*)(b2 + d0);
    float4 cb = *(const float4*)(bi + d0);
    float x0 = a0 + q.x + degf * c2.x + cb.x;
    float x1 = a1 + q.y + degf * c2.y + cb.y;
    float x2 = a2 + q.z + degf * c2.z + cb.z;
    float x3 = a3 + q.w + degf * c2.w + cb.w;
    // LayerNorm over 128 dims (two-pass, all in registers)
    float s = x0 + x1 + x2 + x3;
    #pragma unroll
    for (int off = 16; off; off >>= 1) s += __shfl_xor_sync(0xffffffffu, s, off);
    float mu = s * (1.0f / 128.0f);
    float e0f = x0 - mu, e1f = x1 - mu, e2f = x2 - mu, e3f = x3 - mu;
    float vs = e0f * e0f + e1f * e1f + e2f * e2f + e3f * e3f;
    #pragma unroll
    for (int off = 16; off; off >>= 1) vs += __shfl_xor_sync(0xffffffffu, vs, off);
    float inv = rsqrtf(vs * (1.0f / 128.0f) + 1e-5f);
    float4 w4 = *(const float4*)(lw + d0);
    float4 b4 = *(const float4*)(lb + d0);
    float4 o;
    o.x = fmaxf(e0f * inv * w4.x + b4.x, 0.f);
    o.y = fmaxf(e1f * inv * w4.y + b4.y, 0.f);
    o.z = fmaxf(e2f * inv * w4.z + b4.z, 0.f);
    o.w = fmaxf(e3f * inv * w4.w + b4.w, 0.f);
    *(float4*)(out + (size_t)v * 128 + d0) = o;
}

extern "C" void kernel_launch(void* const* d_in, const int* in_sizes, int n_in,
                              void* d_out, int out_size) {
    const float* x    = (const float*)d_in[0];
    const float* ea   = (const float*)d_in[1];
    const float* linw = (const float*)d_in[2];
    const float* ew1  = (const float*)d_in[3];
    const float* eb1  = (const float*)d_in[4];
    const float* ew2  = (const float*)d_in[5];
    const float* eb2  = (const float*)d_in[6];
    const float* bias = (const float*)d_in[7];
    const float* lnw  = (const float*)d_in[8];
    const float* lnb  = (const float*)d_in[9];
    const int*   eidx = (const int*)d_in[10];
    const int* rowp = eidx;
    const int* colp = eidx + EE;
    float* out = (float*)d_out;

    cudaFuncSetAttribute(k_gemm, cudaFuncAttributeMaxDynamicSharedMemorySize, 98304);

    float *hx, *Q, *S, *h;
    cudaGetSymbolAddress((void**)&hx, g_hx);
    cudaGetSymbolAddress((void**)&Q,  g_Q);
    cudaGetSymbolAddress((void**)&S,  g_S);
    cudaGetSymbolAddress((void**)&h,  g_h);

    // CSR build + norm weights + sorted edge data
    k_zero<<<(NN + 255) / 256, 256>>>();
    k_hist<<<(EE + 255) / 256, 256>>>(colp);
    k_dis<<<(NN + 255) / 256, 256>>>();
    k_scan<<<1, 1024>>>();
    k_scatter<<<(EE + 255) / 256, 256>>>(rowp, colp, ea);

    // edge-MLP hidden + segment-sum for all 3 layers in one pass
    k_spass<<<(NN * LLAY + 7) / 8, 256>>>(ew1, eb1);

    for (int l = 0; l < LLAY; l++) {
        const float* hin = (l == 0) ? x : h;
        k_gemm<<<(NN + 63) / 64, 256, 98304>>>(hin, 128, linw + (size_t)l * 128 * 128, hx, NN);
        k_gemm<<<(NN + 63) / 64, 256, 98304>>>(S + l * 128, DH * LLAY, ew2 + (size_t)l * 128 * 128, Q, NN);
        float* ho = (l == LLAY - 1) ? out : h;
        k_msgln<<<(NN * 32 + 255) / 256, 256>>>(hx, Q, eb2 + l * 128, bias + l * 128,
                                                lnw + l * 128, lnb + l * 128, ho);
    }
}